// round 15
// baseline (speedup 1.0000x reference)
#include <cuda_runtime.h>
#include <cstdint>

// ===========================================================================
// LoRALinear: out = x @ (W + A@B); bias tail written only if out_size has room.
//   x:[8192,4096] W:[4096,4096] bias:[4096] A:[4096,16] B:[16,4096], all f32
//
// R15 (from R14 WIN @2061us; tensor=46%, occ=12%, regs=230 -> latency-bound):
//   - GEMM: 4-stage cp.async pipeline with CORRECT ordering (wait -> sync ->
//     issue into the barrier-protected stage -> commit -> MMA). R9's cp.async
//     corruption was an inter-warp race (loads issued before the sync), not
//     the instruction. Drops the 32-reg LDG buffer; 81920B dynamic smem.
//   - x pre-rounded to tf32 (g_x32) since cp.async can't convert in flight.
//   - prep / check / f32x2 fallback unchanged (validated safety net).
// ===========================================================================

#define SEQ  8192
#define DIN  4096
#define DOUT 4096
#define RANK 16

__device__ float g_Wp [(size_t)DIN * DOUT];   // 64 MB [k][n] exact W+lora
__device__ float g_WpT[(size_t)DOUT * DIN];   // 64 MB [n][k] rna(tf32)
__device__ float g_x32[(size_t)SEQ * DIN];    // 128 MB rna(tf32) x
__device__ int   g_flag;
__device__ int   g_ab_swap;

// ---------------- helpers ---------------------------------------------------
__device__ __forceinline__ uint32_t smem_u32(const void* p) {
    uint32_t a;
    asm("{ .reg .u64 t; cvta.to.shared.u64 t, %1; cvt.u32.u64 %0, t; }" : "=r"(a) : "l"(p));
    return a;
}
__device__ __forceinline__ void cp16(uint32_t s, const void* g) {
    asm volatile("cp.async.cg.shared.global [%0], [%1], 16;" :: "r"(s), "l"(g) : "memory");
}
#define CP_COMMIT() asm volatile("cp.async.commit_group;" ::: "memory")
#define CP_WAIT(n)  asm volatile("cp.async.wait_group %0;" :: "n"(n) : "memory")

__device__ __forceinline__ float rna_tf32(float v) {
    uint32_t b;
    asm("cvt.rna.tf32.f32 %0, %1;" : "=r"(b) : "f"(v));
    return __uint_as_float(b);
}
__device__ __forceinline__ void mma_tf32(float* c, const uint32_t* a, const uint32_t* b) {
    asm volatile(
        "mma.sync.aligned.m16n8k8.row.col.f32.tf32.tf32.f32 "
        "{%0,%1,%2,%3}, {%4,%5,%6,%7}, {%8,%9}, {%0,%1,%2,%3};"
        : "+f"(c[0]), "+f"(c[1]), "+f"(c[2]), "+f"(c[3])
        : "r"(a[0]), "r"(a[1]), "r"(a[2]), "r"(a[3]), "r"(b[0]), "r"(b[1]));
}
__device__ __forceinline__ void fma2(unsigned long long& d,
                                     unsigned long long a, unsigned long long b) {
    asm("fma.rn.f32x2 %0, %1, %2, %0;" : "+l"(d) : "l"(a), "l"(b));
}
__device__ __forceinline__ unsigned long long dup2(float v) {
    unsigned long long r;
    uint32_t b = __float_as_uint(v);
    asm("mov.b64 %0, {%1, %1};" : "=l"(r) : "r"(b));
    return r;
}

// ---------------------------------------------------------------------------
// id: A vs B by mean-square (A scaled 1/sqrt(4096)); reset g_flag.
// ---------------------------------------------------------------------------
__global__ void id_kernel(const float* __restrict__ P0) {
    __shared__ float red[256];
    const int t = threadIdx.x;
    float s = 0.f;
    for (int i = t; i < 16384; i += 256) { float v = P0[i]; s += v * v; }
    red[t] = s;
    __syncthreads();
    for (int off = 128; off > 0; off >>= 1) {
        if (t < off) red[t] += red[t + off];
        __syncthreads();
    }
    if (t == 0) {
        g_ab_swap = (red[0] * (1.f / 16384.f) > 0.05f) ? 1 : 0;
        g_flag = 0;
    }
}

// ---------------------------------------------------------------------------
// round x to tf32 (rna) once; GEMM cp.asyncs from this.
// ---------------------------------------------------------------------------
__global__ void round_x_kernel(const float4* __restrict__ x, float4* __restrict__ dst) {
    size_t i = (size_t)blockIdx.x * blockDim.x + threadIdx.x;
    float4 v = x[i];
    v.x = rna_tf32(v.x); v.y = rna_tf32(v.y);
    v.z = rna_tf32(v.z); v.w = rna_tf32(v.w);
    dst[i] = v;
}

// ---------------------------------------------------------------------------
// prep: g_Wp[k][n] = W + lora (exact)  AND  g_WpT[n][k] = rna(g_Wp) fused.
// ---------------------------------------------------------------------------
__global__ void prep_kn_kernel(const float* __restrict__ W,
                               const float* __restrict__ P0,
                               const float* __restrict__ P1) {
    const float* A = g_ab_swap ? P1 : P0;
    const float* B = g_ab_swap ? P0 : P1;
    __shared__ float tA[32][17];
    __shared__ float tB[16][33];
    __shared__ float tO[32][33];
    const int n0 = blockIdx.x * 32;
    const int k0 = blockIdx.y * 32;
    const int tx = threadIdx.x, ty = threadIdx.y;   // 32 x 8
    const int t = ty * 32 + tx;
#pragma unroll
    for (int i = 0; i < 2; i++) {
        int e = t + 256 * i;
        tA[e / 16][e % 16] = A[(size_t)(k0 + e / 16) * RANK + (e % 16)];
        tB[e / 32][e % 32] = B[(size_t)(e / 32) * DOUT + n0 + (e % 32)];
    }
    __syncthreads();
#pragma unroll
    for (int i = 0; i < 4; i++) {
        int kk = ty + 8 * i;
        float acc = W[(size_t)(k0 + kk) * DOUT + n0 + tx];
#pragma unroll
        for (int r = 0; r < RANK; r++) acc = fmaf(tA[kk][r], tB[r][tx], acc);
        g_Wp[(size_t)(k0 + kk) * DOUT + n0 + tx] = acc;
        tO[kk][tx] = acc;
    }
    __syncthreads();
#pragma unroll
    for (int i = 0; i < 4; i++) {
        int nn = ty + 8 * i;
        g_WpT[(size_t)(n0 + nn) * DIN + k0 + tx] = rna_tf32(tO[tx][nn]);
    }
}

__global__ void bias_copy_kernel(const float* __restrict__ b, float* __restrict__ dst) {
    int i = blockIdx.x * 256 + threadIdx.x;
    if (i < DOUT) dst[i] = b[i];
}

// ===========================================================================
// PRIMARY: mma tf32 GEMM. CTA 128x128, BK=16, 128 threads = 4 warps (2x2),
// warp tile 64x64. 4-stage cp.async pipeline, 81920 B dynamic smem (opt-in).
// Iter i: wait(2) [stage i landed] -> sync [also protects stage (i+3)&3,
// last read in iter i-1] -> issue loads stage i+3 -> commit -> MMA stage i.
// ===========================================================================
static constexpr int APAD = 20;            // (20g+tq) mod 32 hits all 32 banks
static constexpr int STAGE_F = 2 * 128 * APAD;            // floats per stage
static constexpr int STAGE_BYTES = STAGE_F * 4;           // 20480
static constexpr int B_OFF_F = 128 * APAD;                // B offset in floats
static constexpr int GSMEM = 4 * STAGE_BYTES;             // 81920
static constexpr int NITER = DIN / 16;                    // 256
static constexpr int FNT = DOUT / 128;     // 32
static constexpr int FMT = SEQ / 128;      // 64

__global__ __launch_bounds__(128, 2)
void gemm_mma_kernel(float* __restrict__ out) {
    extern __shared__ __align__(16) float smem[];
    const uint32_t su = smem_u32(smem);
    const int tid = threadIdx.x;                       // 128
    const int wid = tid >> 5, lid = tid & 31;
    const int g = lid >> 2, tq = lid & 3;
    const int wm0 = (wid >> 1) * 64;                   // warps 2x2 over 128x128
    const int wn0 = (wid & 1) * 64;

    // supertile swizzle: groups of 8 m-tiles sweep all n-tiles (L2 reuse)
    const int bid = blockIdx.x;
    const int m0 = ((bid >> 8) * 8 + (bid & 7)) * 128;
    const int n0 = ((bid & 255) >> 3) * 128;

    const int ldrow = tid >> 2, ldq = tid & 3;         // rows 0..31(+32p), q 0..3
    const float* gx = g_x32 + (size_t)(m0 + ldrow) * DIN + ldq * 4;
    const float* gw = g_WpT + (size_t)(n0 + ldrow) * DIN + ldq * 4;
    const uint32_t sRowOff = (ldrow * APAD + ldq * 4) * 4;

    auto LOAD_STAGE = [&](int s, int kc) {
        uint32_t base = su + s * STAGE_BYTES;
#pragma unroll
        for (int p = 0; p < 4; p++) {
            cp16(base + sRowOff + (32 * p) * APAD * 4,
                 gx + (size_t)(32 * p) * DIN + kc);
            cp16(base + B_OFF_F * 4 + sRowOff + (32 * p) * APAD * 4,
                 gw + (size_t)(32 * p) * DIN + kc);
        }
    };

    float acc[4][8][4];
#pragma unroll
    for (int i = 0; i < 4; i++)
#pragma unroll
        for (int j = 0; j < 8; j++)
#pragma unroll
            for (int q = 0; q < 4; q++) acc[i][j][q] = 0.f;

    // prologue: stages 0..2
    LOAD_STAGE(0, 0);  CP_COMMIT();
    LOAD_STAGE(1, 16); CP_COMMIT();
    LOAD_STAGE(2, 32); CP_COMMIT();

    for (int i = 0; i < NITER; i++) {
        CP_WAIT(2);                       // stage i's group retired
        __syncthreads();                  // all warps: stage i visible; stage
                                          // (i+3)&3 reads (iter i-1) done
        if (i + 3 < NITER) LOAD_STAGE((i + 3) & 3, (i + 3) * 16);
        CP_COMMIT();                      // keep one group per iteration

        const float* st = smem + (i & 3) * STAGE_F;
        const uint32_t* As = reinterpret_cast<const uint32_t*>(st);
        const uint32_t* Bs = reinterpret_cast<const uint32_t*>(st + B_OFF_F);
#pragma unroll
        for (int kb = 0; kb < 2; kb++) {
            uint32_t af[4][4], bf[8][2];
            const int kc = kb * 8 + tq;
#pragma unroll
            for (int mi = 0; mi < 4; mi++) {
                const uint32_t* p = As + (wm0 + mi * 16 + g) * APAD + kc;
                af[mi][0] = p[0];
                af[mi][1] = p[8 * APAD];
                af[mi][2] = p[4];
                af[mi][3] = p[8 * APAD + 4];
            }
#pragma unroll
            for (int ni = 0; ni < 8; ni++) {
                const uint32_t* p = Bs + (wn0 + ni * 8 + g) * APAD + kc;
                bf[ni][0] = p[0];
                bf[ni][1] = p[4];
            }
#pragma unroll
            for (int mi = 0; mi < 4; mi++)
#pragma unroll
                for (int ni = 0; ni < 8; ni++)
                    mma_tf32(acc[mi][ni], af[mi], bf[ni]);
        }
    }

#pragma unroll
    for (int mi = 0; mi < 4; mi++) {
        const int row = m0 + wm0 + mi * 16 + g;
#pragma unroll
        for (int ni = 0; ni < 8; ni++) {
            const int col = n0 + wn0 + ni * 8 + tq * 2;
            *reinterpret_cast<float2*>(out + (size_t)row * DOUT + col) =
                make_float2(acc[mi][ni][0], acc[mi][ni][1]);
            *reinterpret_cast<float2*>(out + (size_t)(row + 8) * DOUT + col) =
                make_float2(acc[mi][ni][2], acc[mi][ni][3]);
        }
    }
}

// ===========================================================================
// Fast check: one sample per 128x128 tile vs validated g_Wp. 2048 blocks.
// ===========================================================================
__global__ void check_kernel(const float* __restrict__ out,
                             const float* __restrict__ x) {
    const int b = blockIdx.x;                       // 0..2047
    const int m = (b >> 5) * 128 + ((b * 37) & 127);
    const int n = (b & 31) * 128 + ((b * 59) & 127);
    const int t = threadIdx.x;                      // 128
    float s = 0.f;
    for (int k = t; k < DIN; k += 128)
        s = fmaf(x[(size_t)m * DIN + k], g_Wp[(size_t)k * DOUT + n], s);
    __shared__ float red[128];
    red[t] = s;
    __syncthreads();
    for (int o = 64; o > 0; o >>= 1) {
        if (t < o) red[t] += red[t + o];
        __syncthreads();
    }
    if (t == 0) {
        float acc = red[0];
        float got = out[(size_t)m * DOUT + n];
        if (fabsf(got - acc) > 0.05f + 0.02f * fabsf(acc))
            atomicAdd(&g_flag, 1);
    }
}

// ===========================================================================
// Fallback: exact fp32 via packed fma.rn.f32x2 (validated). Gated on g_flag.
// ===========================================================================
static constexpr int P2 = 132;

__global__ __launch_bounds__(256, 2)
void gemm_f32x2_kernel(const float* __restrict__ x, float* __restrict__ out) {
    if (g_flag == 0) return;
    __shared__ __align__(16) float Xs[2][16][P2];
    __shared__ __align__(16) float Ws[2][16][P2];
    const int t = threadIdx.x;
    const int tm2 = t >> 4, tn2 = t & 15;

    const int bid = blockIdx.x;
    const int m0 = ((bid >> 8) * 8 + (bid & 7)) * 128;
    const int n0 = ((bid & 255) >> 3) * 128;

    unsigned long long acc2[8][4];
#pragma unroll
    for (int i = 0; i < 8; i++)
#pragma unroll
        for (int j = 0; j < 4; j++) acc2[i][j] = 0ULL;

    float4 rx[2], rw[2];
    auto LOADG = [&](int kc) {
#pragma unroll
        for (int j = 0; j < 2; j++) {
            int idx = j * 256 + t;
            int m = idx >> 2, q = idx & 3;
            rx[j] = *reinterpret_cast<const float4*>(
                x + (size_t)(m0 + m) * DIN + kc + q * 4);
            int kk = idx >> 5, qn = idx & 31;
            rw[j] = *reinterpret_cast<const float4*>(
                g_Wp + (size_t)(kc + kk) * DOUT + n0 + qn * 4);
        }
    };
    auto STORES = [&](int buf) {
#pragma unroll
        for (int j = 0; j < 2; j++) {
            int idx = j * 256 + t;
            int m = idx >> 2, q = idx & 3;
            Xs[buf][q * 4 + 0][m] = rx[j].x;
            Xs[buf][q * 4 + 1][m] = rx[j].y;
            Xs[buf][q * 4 + 2][m] = rx[j].z;
            Xs[buf][q * 4 + 3][m] = rx[j].w;
            int kk = idx >> 5, qn = idx & 31;
            *reinterpret_cast<float4*>(&Ws[buf][kk][qn * 4]) = rw[j];
        }
    };

    LOADG(0);
    STORES(0);
    __syncthreads();

    for (int i = 0; i < DIN / 16; i++) {
        if (i + 1 < DIN / 16) LOADG((i + 1) * 16);
        const int buf = i & 1;
#pragma unroll
        for (int kk = 0; kk < 16; kk++) {
            unsigned long long b2[4];
#pragma unroll
            for (int jj = 0; jj < 4; jj++)
                b2[jj] = *reinterpret_cast<const unsigned long long*>(
                    &Ws[buf][kk][tn2 * 2 + 32 * jj]);
#pragma unroll
            for (int ii = 0; ii < 8; ii++) {
                unsigned long long a2 = dup2(Xs[buf][kk][tm2 + 16 * ii]);
#pragma unroll
                for (int jj = 0; jj < 4; jj++)
                    fma2(acc2[ii][jj], a2, b2[jj]);
            }
        }
        if (i + 1 < DIN / 16) STORES(buf ^ 1);
        __syncthreads();
    }

#pragma unroll
    for (int ii = 0; ii < 8; ii++) {
        const int row = m0 + tm2 + 16 * ii;
#pragma unroll
        for (int jj = 0; jj < 4; jj++) {
            uint32_t lo, hi;
            asm("mov.b64 {%0, %1}, %2;" : "=r"(lo), "=r"(hi) : "l"(acc2[ii][jj]));
            *reinterpret_cast<float2*>(out + (size_t)row * DOUT + n0 + tn2 * 2 + 32 * jj) =
                make_float2(__uint_as_float(lo), __uint_as_float(hi));
        }
    }
}

// ---------------------------------------------------------------------------
extern "C" void kernel_launch(void* const* d_in, const int* in_sizes, int n_in,
                              void* d_out, int out_size) {
    const float *x = nullptr, *W = nullptr, *bias = nullptr;
    const float *P0 = nullptr, *P1 = nullptr;
    for (int i = 0; i < n_in; i++) {
        const float* p = (const float*)d_in[i];
        int sz = in_sizes[i];
        if      (sz == SEQ * DIN)   x = p;
        else if (sz == DIN * DOUT)  W = p;
        else if (sz == DOUT)        bias = p;
        else if (sz == DIN * RANK) { if (!P0) P0 = p; else P1 = p; }
    }
    if (!x || !W || !bias || !P0 || !P1) {
        x = (const float*)d_in[0]; W = (const float*)d_in[1];
        bias = (const float*)d_in[2];
        P0 = (const float*)d_in[3]; P1 = (const float*)d_in[4];
    }
    float* out = (float*)d_out;

    cudaFuncSetAttribute(gemm_mma_kernel,
                         cudaFuncAttributeMaxDynamicSharedMemorySize, GSMEM);

    id_kernel<<<1, 256>>>(P0);
    round_x_kernel<<<(SEQ * DIN / 4) / 256, 256>>>((const float4*)x, (float4*)g_x32);
    prep_kn_kernel<<<dim3(DOUT / 32, DIN / 32), dim3(32, 8)>>>(W, P0, P1);

    if (out_size >= SEQ * DOUT + DOUT)
        bias_copy_kernel<<<(DOUT + 255) / 256, 256>>>(bias, out + (size_t)SEQ * DOUT);

    gemm_mma_kernel<<<FMT * FNT, 128, GSMEM>>>(out);
    check_kernel<<<2048, 128>>>(out, x);
    gemm_f32x2_kernel<<<FMT * FNT, 256>>>(x, out);
}

// round 16
// speedup vs baseline: 3.3671x; 3.3671x over previous
#include <cuda_runtime.h>
#include <cstdint>

// ===========================================================================
// LoRALinear: out = x @ (W + A@B); bias tail written only if out_size has room.
//   x:[8192,4096] W:[4096,4096] bias:[4096] A:[4096,16] B:[16,4096], all f32
//
// R16 (from R14 WIN @2061us; R15's cp.async retry failed again -> cp.async
// abandoned for good this session):
//   - GEMM: R14's validated plain-LDG reg-double-buffer mechanism, BK 16->32.
//     1024 tensor cyc/iter now covers the ~600cyc LDG->STS dependency that was
//     exposed at BK=16; syncs halve. Warp tile 64x64, fragments unchanged.
//     smem 73728B dynamic (opt-in), APAD=36 (16B-aligned rows, conflict-free).
//   - prep / check / f32x2 fallback unchanged (validated safety net).
// ===========================================================================

#define SEQ  8192
#define DIN  4096
#define DOUT 4096
#define RANK 16

__device__ float g_Wp [(size_t)DIN * DOUT];   // 64 MB [k][n] exact W+lora
__device__ float g_WpT[(size_t)DOUT * DIN];   // 64 MB [n][k] rna(tf32)
__device__ int   g_flag;
__device__ int   g_ab_swap;

// ---------------- helpers ---------------------------------------------------
__device__ __forceinline__ float rna_tf32(float v) {
    uint32_t b;
    asm("cvt.rna.tf32.f32 %0, %1;" : "=r"(b) : "f"(v));
    return __uint_as_float(b);
}
__device__ __forceinline__ void mma_tf32(float* c, const uint32_t* a, const uint32_t* b) {
    asm volatile(
        "mma.sync.aligned.m16n8k8.row.col.f32.tf32.tf32.f32 "
        "{%0,%1,%2,%3}, {%4,%5,%6,%7}, {%8,%9}, {%0,%1,%2,%3};"
        : "+f"(c[0]), "+f"(c[1]), "+f"(c[2]), "+f"(c[3])
        : "r"(a[0]), "r"(a[1]), "r"(a[2]), "r"(a[3]), "r"(b[0]), "r"(b[1]));
}
__device__ __forceinline__ void fma2(unsigned long long& d,
                                     unsigned long long a, unsigned long long b) {
    asm("fma.rn.f32x2 %0, %1, %2, %0;" : "+l"(d) : "l"(a), "l"(b));
}
__device__ __forceinline__ unsigned long long dup2(float v) {
    unsigned long long r;
    uint32_t b = __float_as_uint(v);
    asm("mov.b64 %0, {%1, %1};" : "=l"(r) : "r"(b));
    return r;
}

// ---------------------------------------------------------------------------
// id: A vs B by mean-square (A scaled 1/sqrt(4096)); reset g_flag.
// ---------------------------------------------------------------------------
__global__ void id_kernel(const float* __restrict__ P0) {
    __shared__ float red[256];
    const int t = threadIdx.x;
    float s = 0.f;
    for (int i = t; i < 16384; i += 256) { float v = P0[i]; s += v * v; }
    red[t] = s;
    __syncthreads();
    for (int off = 128; off > 0; off >>= 1) {
        if (t < off) red[t] += red[t + off];
        __syncthreads();
    }
    if (t == 0) {
        g_ab_swap = (red[0] * (1.f / 16384.f) > 0.05f) ? 1 : 0;
        g_flag = 0;
    }
}

// ---------------------------------------------------------------------------
// prep: g_Wp[k][n] = W + lora (exact)  AND  g_WpT[n][k] = rna(g_Wp) fused.
// ---------------------------------------------------------------------------
__global__ void prep_kn_kernel(const float* __restrict__ W,
                               const float* __restrict__ P0,
                               const float* __restrict__ P1) {
    const float* A = g_ab_swap ? P1 : P0;
    const float* B = g_ab_swap ? P0 : P1;
    __shared__ float tA[32][17];
    __shared__ float tB[16][33];
    __shared__ float tO[32][33];
    const int n0 = blockIdx.x * 32;
    const int k0 = blockIdx.y * 32;
    const int tx = threadIdx.x, ty = threadIdx.y;   // 32 x 8
    const int t = ty * 32 + tx;
#pragma unroll
    for (int i = 0; i < 2; i++) {
        int e = t + 256 * i;
        tA[e / 16][e % 16] = A[(size_t)(k0 + e / 16) * RANK + (e % 16)];
        tB[e / 32][e % 32] = B[(size_t)(e / 32) * DOUT + n0 + (e % 32)];
    }
    __syncthreads();
#pragma unroll
    for (int i = 0; i < 4; i++) {
        int kk = ty + 8 * i;
        float acc = W[(size_t)(k0 + kk) * DOUT + n0 + tx];
#pragma unroll
        for (int r = 0; r < RANK; r++) acc = fmaf(tA[kk][r], tB[r][tx], acc);
        g_Wp[(size_t)(k0 + kk) * DOUT + n0 + tx] = acc;
        tO[kk][tx] = acc;
    }
    __syncthreads();
#pragma unroll
    for (int i = 0; i < 4; i++) {
        int nn = ty + 8 * i;
        g_WpT[(size_t)(n0 + nn) * DIN + k0 + tx] = rna_tf32(tO[tx][nn]);
    }
}

__global__ void bias_copy_kernel(const float* __restrict__ b, float* __restrict__ dst) {
    int i = blockIdx.x * 256 + threadIdx.x;
    if (i < DOUT) dst[i] = b[i];
}

// ===========================================================================
// PRIMARY: mma tf32 GEMM. CTA 128x128, BK=32, 128 threads = 4 warps (2x2),
// warp tile 64x64. Plain-LDG register-double-buffered pipeline (validated
// mechanism). Dynamic smem 2 x 2 x 128 x 36 x 4 = 73728 B (opt-in).
// ===========================================================================
static constexpr int APAD = 36;            // rows 144B (16B-mult); 36g%32=4g
static constexpr int TILE_F = 128 * APAD;                 // floats per op tile
static constexpr int STAGE_F = 2 * TILE_F;                // A + B
static constexpr int GSMEM = 2 * STAGE_F * 4;             // 73728
static constexpr int NITER = DIN / 32;                    // 128
static constexpr int FNT = DOUT / 128;     // 32
static constexpr int FMT = SEQ / 128;      // 64

__global__ __launch_bounds__(128, 2)
void gemm_mma_kernel(const float* __restrict__ x, float* __restrict__ out) {
    extern __shared__ __align__(16) float smem[];
    const int tid = threadIdx.x;                       // 128
    const int wid = tid >> 5, lid = tid & 31;
    const int g = lid >> 2, tq = lid & 3;
    const int wm0 = (wid >> 1) * 64;                   // warps 2x2 over 128x128
    const int wn0 = (wid & 1) * 64;

    // supertile swizzle: groups of 8 m-tiles sweep all n-tiles (L2 reuse)
    const int bid = blockIdx.x;
    const int m0 = ((bid >> 8) * 8 + (bid & 7)) * 128;
    const int n0 = ((bid & 255) >> 3) * 128;

    const int ldrow = tid >> 3, ldq = tid & 7;         // 16 rows/pass, q 0..7
    const float* gx = x     + (size_t)(m0 + ldrow) * DIN + ldq * 4;
    const float* gw = g_WpT + (size_t)(n0 + ldrow) * DIN + ldq * 4;
    const int sOff = ldrow * APAD + ldq * 4;

    float acc[4][8][4];
#pragma unroll
    for (int i = 0; i < 4; i++)
#pragma unroll
        for (int j = 0; j < 8; j++)
#pragma unroll
            for (int q = 0; q < 4; q++) acc[i][j][q] = 0.f;

    float4 ra[8], rb[8];                               // 8 row-passes each
    auto LOADG = [&](int kc) {
#pragma unroll
        for (int p = 0; p < 8; p++) {
            ra[p] = *reinterpret_cast<const float4*>(gx + (size_t)(16 * p) * DIN + kc);
            rb[p] = *reinterpret_cast<const float4*>(gw + (size_t)(16 * p) * DIN + kc);
        }
    };
    auto STORES = [&](int buf) {
        float* sA = smem + buf * STAGE_F;
        float* sB = sA + TILE_F;
#pragma unroll
        for (int p = 0; p < 8; p++) {
            float4 va = ra[p];
            va.x = rna_tf32(va.x); va.y = rna_tf32(va.y);
            va.z = rna_tf32(va.z); va.w = rna_tf32(va.w);
            *reinterpret_cast<float4*>(&sA[sOff + (16 * p) * APAD]) = va;
            *reinterpret_cast<float4*>(&sB[sOff + (16 * p) * APAD]) = rb[p];
        }
    };

    LOADG(0);
    STORES(0);
    __syncthreads();

    for (int i = 0; i < NITER; i++) {
        if (i + 1 < NITER) LOADG((i + 1) * 32);        // ~1024 tensor cyc ahead

        const int buf = i & 1;
        const uint32_t* As = reinterpret_cast<const uint32_t*>(smem + buf * STAGE_F);
        const uint32_t* Bs = As + TILE_F;
#pragma unroll
        for (int kb = 0; kb < 4; kb++) {
            uint32_t af[4][4], bf[8][2];
            const int kc = kb * 8 + tq;
#pragma unroll
            for (int mi = 0; mi < 4; mi++) {
                const uint32_t* p = As + (wm0 + mi * 16 + g) * APAD + kc;
                af[mi][0] = p[0];
                af[mi][1] = p[8 * APAD];
                af[mi][2] = p[4];
                af[mi][3] = p[8 * APAD + 4];
            }
#pragma unroll
            for (int ni = 0; ni < 8; ni++) {
                const uint32_t* p = Bs + (wn0 + ni * 8 + g) * APAD + kc;
                bf[ni][0] = p[0];
                bf[ni][1] = p[4];
            }
#pragma unroll
            for (int mi = 0; mi < 4; mi++)
#pragma unroll
                for (int ni = 0; ni < 8; ni++)
                    mma_tf32(acc[mi][ni], af[mi], bf[ni]);
        }

        if (i + 1 < NITER) STORES(buf ^ 1);   // buf^1 reads finished at i-1
        __syncthreads();
    }

#pragma unroll
    for (int mi = 0; mi < 4; mi++) {
        const int row = m0 + wm0 + mi * 16 + g;
#pragma unroll
        for (int ni = 0; ni < 8; ni++) {
            const int col = n0 + wn0 + ni * 8 + tq * 2;
            *reinterpret_cast<float2*>(out + (size_t)row * DOUT + col) =
                make_float2(acc[mi][ni][0], acc[mi][ni][1]);
            *reinterpret_cast<float2*>(out + (size_t)(row + 8) * DOUT + col) =
                make_float2(acc[mi][ni][2], acc[mi][ni][3]);
        }
    }
}

// ===========================================================================
// Fast check: one sample per 128x128 tile vs validated g_Wp. 2048 blocks.
// ===========================================================================
__global__ void check_kernel(const float* __restrict__ out,
                             const float* __restrict__ x) {
    const int b = blockIdx.x;                       // 0..2047
    const int m = (b >> 5) * 128 + ((b * 37) & 127);
    const int n = (b & 31) * 128 + ((b * 59) & 127);
    const int t = threadIdx.x;                      // 128
    float s = 0.f;
    for (int k = t; k < DIN; k += 128)
        s = fmaf(x[(size_t)m * DIN + k], g_Wp[(size_t)k * DOUT + n], s);
    __shared__ float red[128];
    red[t] = s;
    __syncthreads();
    for (int o = 64; o > 0; o >>= 1) {
        if (t < o) red[t] += red[t + o];
        __syncthreads();
    }
    if (t == 0) {
        float acc = red[0];
        float got = out[(size_t)m * DOUT + n];
        if (fabsf(got - acc) > 0.05f + 0.02f * fabsf(acc))
            atomicAdd(&g_flag, 1);
    }
}

// ===========================================================================
// Fallback: exact fp32 via packed fma.rn.f32x2 (validated). Gated on g_flag.
// ===========================================================================
static constexpr int P2 = 132;

__global__ __launch_bounds__(256, 2)
void gemm_f32x2_kernel(const float* __restrict__ x, float* __restrict__ out) {
    if (g_flag == 0) return;
    __shared__ __align__(16) float Xs[2][16][P2];
    __shared__ __align__(16) float Ws[2][16][P2];
    const int t = threadIdx.x;
    const int tm2 = t >> 4, tn2 = t & 15;

    const int bid = blockIdx.x;
    const int m0 = ((bid >> 8) * 8 + (bid & 7)) * 128;
    const int n0 = ((bid & 255) >> 3) * 128;

    unsigned long long acc2[8][4];
#pragma unroll
    for (int i = 0; i < 8; i++)
#pragma unroll
        for (int j = 0; j < 4; j++) acc2[i][j] = 0ULL;

    float4 rx[2], rw[2];
    auto LOADG = [&](int kc) {
#pragma unroll
        for (int j = 0; j < 2; j++) {
            int idx = j * 256 + t;
            int m = idx >> 2, q = idx & 3;
            rx[j] = *reinterpret_cast<const float4*>(
                x + (size_t)(m0 + m) * DIN + kc + q * 4);
            int kk = idx >> 5, qn = idx & 31;
            rw[j] = *reinterpret_cast<const float4*>(
                g_Wp + (size_t)(kc + kk) * DOUT + n0 + qn * 4);
        }
    };
    auto STORES = [&](int buf) {
#pragma unroll
        for (int j = 0; j < 2; j++) {
            int idx = j * 256 + t;
            int m = idx >> 2, q = idx & 3;
            Xs[buf][q * 4 + 0][m] = rx[j].x;
            Xs[buf][q * 4 + 1][m] = rx[j].y;
            Xs[buf][q * 4 + 2][m] = rx[j].z;
            Xs[buf][q * 4 + 3][m] = rx[j].w;
            int kk = idx >> 5, qn = idx & 31;
            *reinterpret_cast<float4*>(&Ws[buf][kk][qn * 4]) = rw[j];
        }
    };

    LOADG(0);
    STORES(0);
    __syncthreads();

    for (int i = 0; i < DIN / 16; i++) {
        if (i + 1 < DIN / 16) LOADG((i + 1) * 16);
        const int buf = i & 1;
#pragma unroll
        for (int kk = 0; kk < 16; kk++) {
            unsigned long long b2[4];
#pragma unroll
            for (int jj = 0; jj < 4; jj++)
                b2[jj] = *reinterpret_cast<const unsigned long long*>(
                    &Ws[buf][kk][tn2 * 2 + 32 * jj]);
#pragma unroll
            for (int ii = 0; ii < 8; ii++) {
                unsigned long long a2 = dup2(Xs[buf][kk][tm2 + 16 * ii]);
#pragma unroll
                for (int jj = 0; jj < 4; jj++)
                    fma2(acc2[ii][jj], a2, b2[jj]);
            }
        }
        if (i + 1 < DIN / 16) STORES(buf ^ 1);
        __syncthreads();
    }

#pragma unroll
    for (int ii = 0; ii < 8; ii++) {
        const int row = m0 + tm2 + 16 * ii;
#pragma unroll
        for (int jj = 0; jj < 4; jj++) {
            uint32_t lo, hi;
            asm("mov.b64 {%0, %1}, %2;" : "=r"(lo), "=r"(hi) : "l"(acc2[ii][jj]));
            *reinterpret_cast<float2*>(out + (size_t)row * DOUT + n0 + tn2 * 2 + 32 * jj) =
                make_float2(__uint_as_float(lo), __uint_as_float(hi));
        }
    }
}

// ---------------------------------------------------------------------------
extern "C" void kernel_launch(void* const* d_in, const int* in_sizes, int n_in,
                              void* d_out, int out_size) {
    const float *x = nullptr, *W = nullptr, *bias = nullptr;
    const float *P0 = nullptr, *P1 = nullptr;
    for (int i = 0; i < n_in; i++) {
        const float* p = (const float*)d_in[i];
        int sz = in_sizes[i];
        if      (sz == SEQ * DIN)   x = p;
        else if (sz == DIN * DOUT)  W = p;
        else if (sz == DOUT)        bias = p;
        else if (sz == DIN * RANK) { if (!P0) P0 = p; else P1 = p; }
    }
    if (!x || !W || !bias || !P0 || !P1) {
        x = (const float*)d_in[0]; W = (const float*)d_in[1];
        bias = (const float*)d_in[2];
        P0 = (const float*)d_in[3]; P1 = (const float*)d_in[4];
    }
    float* out = (float*)d_out;

    cudaFuncSetAttribute(gemm_mma_kernel,
                         cudaFuncAttributeMaxDynamicSharedMemorySize, GSMEM);

    id_kernel<<<1, 256>>>(P0);
    prep_kn_kernel<<<dim3(DOUT / 32, DIN / 32), dim3(32, 8)>>>(W, P0, P1);

    if (out_size >= SEQ * DOUT + DOUT)
        bias_copy_kernel<<<(DOUT + 255) / 256, 256>>>(bias, out + (size_t)SEQ * DOUT);

    gemm_mma_kernel<<<FMT * FNT, 128, GSMEM>>>(x, out);
    check_kernel<<<2048, 128>>>(out, x);
    gemm_f32x2_kernel<<<FMT * FNT, 256>>>(x, out);
}